// round 13
// baseline (speedup 1.0000x reference)
#include <cuda_runtime.h>

#define EPS 1e-5f

// scratch (static device globals, no allocation)
__device__ float g_weff_t[256 * 1280];                // [cin][ocg]
__device__ float g_beff[1280];
__device__ float g_wt[9216 * 256];                    // [(tap*1024+ci)][oc], BN-scaled
__device__ float g_bout[256];
__device__ float g_qkv[(size_t)2 * 8192 * 1280];      // [b][pix][ocg]
__device__ float g_ctx[(size_t)2 * 8192 * 1024];      // [b][pix][4*256]

typedef unsigned long long u64;
__device__ __forceinline__ u64 pack2(float a, float b) {
    u64 r; asm("mov.b64 %0, {%1, %2};" : "=l"(r) : "f"(a), "f"(b)); return r;
}
__device__ __forceinline__ void unpack2(u64 v, float& a, float& b) {
    asm("mov.b64 {%0, %1}, %2;" : "=f"(a), "=f"(b) : "l"(v));
}
__device__ __forceinline__ u64 fma2(u64 a, u64 b, u64 c) {
    u64 d; asm("fma.rn.f32x2 %0, %1, %2, %3;" : "=l"(d) : "l"(a), "l"(b), "l"(c)); return d;
}
__device__ __forceinline__ u64 mul2(u64 a, u64 b) {
    u64 d; asm("mul.rn.f32x2 %0, %1, %2;" : "=l"(d) : "l"(a), "l"(b)); return d;
}
__device__ __forceinline__ void cp8(unsigned dst, const void* src) {
    asm volatile("cp.async.ca.shared.global [%0], [%1], 8;" :: "r"(dst), "l"(src));
}
__device__ __forceinline__ void cp16(unsigned dst, const void* src) {
    asm volatile("cp.async.cg.shared.global [%0], [%1], 16;" :: "r"(dst), "l"(src));
}
#define CP_COMMIT asm volatile("cp.async.commit_group;" ::: "memory")
#define CP_WAIT0  asm volatile("cp.async.wait_group 0;" ::: "memory")

// ---- 1) fold conv1x1 + BN ----
__global__ void prep_qkv(const float* qw, const float* qb, const float* qg, const float* qbe,
                         const float* qm, const float* qv, const float* kw, const float* kb,
                         const float* kg, const float* kbe, const float* km, const float* kvv,
                         const float* vw, const float* vb) {
    int ocg = blockIdx.x;
    int s = ocg / 320, r = ocg % 320;
    float sc, be; const float* wsrc;
    if (r < 32) {
        int d = s * 32 + r;
        sc = qg[d] * rsqrtf(qv[d] + EPS);
        be = qb[d] * sc + qbe[d] - qm[d] * sc;
        wsrc = qw + (size_t)d * 256;
    } else if (r < 64) {
        int d = s * 32 + (r - 32);
        sc = kg[d] * rsqrtf(kvv[d] + EPS);
        be = kb[d] * sc + kbe[d] - km[d] * sc;
        wsrc = kw + (size_t)d * 256;
    } else {
        int d = s * 256 + (r - 64);
        sc = 1.0f; be = vb[d];
        wsrc = vw + (size_t)d * 256;
    }
    for (int c = threadIdx.x; c < 256; c += blockDim.x)
        g_weff_t[c * 1280 + ocg] = wsrc[c] * sc;
    if (threadIdx.x == 0) g_beff[ocg] = be;
}

// ---- 2) fold BN into transposed 3x3 weights ----
__global__ void prep_conv(const float* cw, const float* cb, const float* cg,
                          const float* cbe, const float* cm, const float* cv) {
    int blk = blockIdx.x;                 // tap*1024 + ci
    int o = threadIdx.x;
    float sc = cg[o] * rsqrtf(cv[o] + EPS);
    g_wt[(size_t)blk * 256 + o] =
        cw[((size_t)o * 1024 + (blk & 1023)) * 9 + (blk >> 10)] * sc;
    if (blk == 0) g_bout[o] = cb[o] * sc + cbe[o] - cm[o] * sc;
}

// ---- 3) fused QKV GEMM ----
__global__ void __launch_bounds__(256) gemm_qkv(const float* __restrict__ feats) {
    __shared__ __align__(16) float As[16][64];
    __shared__ __align__(16) float Bs[16][64];
    const int tid = threadIdx.x, tx = tid & 15, ty = tid >> 4;
    const int m0 = blockIdx.x << 6, n0 = blockIdx.y << 6;
    const int b = m0 >> 13, pix0 = m0 & 8191;
    u64 acc[4][2];
#pragma unroll
    for (int i = 0; i < 4; i++) { acc[i][0] = 0; acc[i][1] = 0; }
    for (int c0 = 0; c0 < 256; c0 += 16) {
        __syncthreads();
#pragma unroll
        for (int it = 0; it < 4; it++) {
            int idx = tid + it * 256, kk = idx >> 6, mm = idx & 63;
            As[kk][mm] = feats[(size_t)(b * 256 + c0 + kk) * 8192 + pix0 + mm];
            Bs[kk][mm] = g_weff_t[(size_t)(c0 + kk) * 1280 + n0 + mm];
        }
        __syncthreads();
#pragma unroll
        for (int kk = 0; kk < 16; kk++) {
            ulonglong2 b2 = *(const ulonglong2*)&Bs[kk][tx * 4];
#pragma unroll
            for (int i2 = 0; i2 < 4; i2++) {
                float a = As[kk][ty * 4 + i2];
                u64 a2 = pack2(a, a);
                acc[i2][0] = fma2(a2, b2.x, acc[i2][0]);
                acc[i2][1] = fma2(a2, b2.y, acc[i2][1]);
            }
        }
    }
    const float4 bias = *(const float4*)(g_beff + n0 + tx * 4);
#pragma unroll
    for (int i2 = 0; i2 < 4; i2++) {
        float a0, a1, a2, a3;
        unpack2(acc[i2][0], a0, a1);
        unpack2(acc[i2][1], a2, a3);
        *(float4*)(g_qkv + (size_t)(m0 + ty * 4 + i2) * 1280 + n0 + tx * 4) =
            make_float4(a0 + bias.x, a1 + bias.y, a2 + bias.z, a3 + bias.w);
    }
}

// ---- 4) windowed attention: 256 thr, 8 warps x 8 queries; pre-duplicated p-table ----
// dynamic smem layout (floats):
//   q_s   [0 .. 2048)             64 q x 32 ch
//   k_s   [2048 .. 2048+2*1088)   2 bufs x (32 keys x 34)
//   v_s   [4224 .. 4224+2*8192)   2 bufs x (32 keys x 256)
//   p4    [20608 .. 20608+4096)   8 warps x 4 qpairs x 32 keys, float4 = (p2g,p2g,p2g+1,p2g+1)
#define ATTN_SMEM_FLOATS (2048 + 2 * 1088 + 2 * 8192 + 4096)
__global__ void __launch_bounds__(256, 1) attn() {
    extern __shared__ __align__(16) float smf[];
    float* q_s = smf;
    float* k_sb = smf + 2048;
    float* v_sb = smf + 4224;
    float4* p4 = (float4*)(smf + 20608);
    const unsigned k_addr = (unsigned)__cvta_generic_to_shared(k_sb);
    const unsigned v_addr = (unsigned)__cvta_generic_to_shared(v_sb);

    const int tid = threadIdx.x, lane = tid & 31, warp = tid >> 5;   // 8 warps
    const int bid = blockIdx.x;
    const int sidx = bid >> 8, within = bid & 255;
    const int shift = 6 - sidx;
    const int ws = 64 >> sidx;
    const int L = 8192 >> (2 * sidx);
    const int bpwLog = 7 - 2 * sidx;
    const int win = within >> bpwLog;
    const int qblk = within & ((1 << bpwLog) - 1);
    const int batch = win & 1;
    const int ij = win >> 1;
    const int wi = ij >> sidx, wj = ij & ((1 << sidx) - 1);
    const int l0 = qblk << 6;
    const float* qkv_b = g_qkv + (size_t)batch * 8192 * 1280;
    const int chbase = sidx * 320;

    auto pix_of = [&](int l) -> int {
        int half = l & 1, rc = l >> 1;
        int r = rc >> shift, c = rc & (ws - 1);
        return (wi * ws + r) * 128 + half * 64 + wj * ws + c;
    };

    // load queries (once)
    for (int idx = tid; idx < 1024; idx += 256) {
        int ql = idx >> 4, c2 = idx & 15;
        float2 v = *(const float2*)(qkv_b + (size_t)pix_of(l0 + ql) * 1280 + chbase + c2 * 2);
        q_s[ql * 32 + c2 * 2] = v.x; q_s[ql * 32 + c2 * 2 + 1] = v.y;
    }

    auto load_tile = [&](int t, int buf) {
        int m0 = t << 5;
#pragma unroll
        for (int i = 0; i < 2; i++) {   // k tile: 32 keys x 16 ch-pairs
            int idx = tid + i * 256;
            int key = idx >> 4, c2 = idx & 15;
            const float* src = qkv_b + (size_t)pix_of(m0 + key) * 1280 + chbase + 32 + c2 * 2;
            cp8(k_addr + (buf * 1088 + key * 34 + c2 * 2) * 4, src);
        }
#pragma unroll
        for (int i = 0; i < 8; i++) {   // v tile: 32 keys x 64 float4
            int idx = tid + i * 256;
            int key = idx >> 6, c4 = idx & 63;
            const float* src = qkv_b + (size_t)pix_of(m0 + key) * 1280 + chbase + 64 + c4 * 4;
            cp16(v_addr + (buf * 8192 + key * 256 + c4 * 4) * 4, src);
        }
    };

    float den[8], p_reg[8];
    u64 acc[8][4];
#pragma unroll
    for (int q = 0; q < 8; q++) {
        den[q] = 0.f;
        acc[q][0] = acc[q][1] = acc[q][2] = acc[q][3] = 0;
    }
    const float* qbase = q_s + (warp * 8) * 32;
    float4* pw = p4 + warp * 128;                 // 4 qpairs x 32 keys
    const int nt = L >> 5;

    load_tile(0, 0);
    CP_COMMIT;
    CP_WAIT0;
    __syncthreads();

    for (int t = 0; t < nt; t++) {
        int buf = t & 1;
        if (t + 1 < nt) { load_tile(t + 1, buf ^ 1); CP_COMMIT; }

        const float* k_s = k_sb + buf * 1088;
        const float* v_s = v_sb + buf * 8192;

        u64 k2[16];
        const u64* krow = (const u64*)(k_s + lane * 34);
#pragma unroll
        for (int d = 0; d < 16; d++) k2[d] = krow[d];

#pragma unroll
        for (int q = 0; q < 8; q++) {
            const ulonglong2* qrow2 = (const ulonglong2*)(qbase + q * 32);
            u64 s0 = 0, s1 = 0, s2c = 0, s3 = 0;   // 4 chains for ILP
#pragma unroll
            for (int d = 0; d < 4; d++) {
                ulonglong2 qa = qrow2[d];          // LDS.128 broadcast
                ulonglong2 qb = qrow2[d + 4];
                s0 = fma2(k2[2 * d], qa.x, s0);
                s1 = fma2(k2[2 * d + 1], qa.y, s1);
                s2c = fma2(k2[2 * d + 8], qb.x, s2c);
                s3 = fma2(k2[2 * d + 9], qb.y, s3);
            }
            float a0, a1, b0, b1, c0, c1, d0, d1;
            unpack2(s0, a0, a1); unpack2(s1, b0, b1);
            unpack2(s2c, c0, c1); unpack2(s3, d0, d1);
            float p = __expf(((a0 + a1) + (b0 + b1) + (c0 + c1) + (d0 + d1)) *
                             0.17677669529663687f);
            den[q] += p;
            p_reg[q] = p;
        }
        // lane = key: publish duplicated probability pairs (conflict-free STS.128)
        pw[lane] = make_float4(p_reg[0], p_reg[0], p_reg[1], p_reg[1]);
        pw[32 + lane] = make_float4(p_reg[2], p_reg[2], p_reg[3], p_reg[3]);
        pw[64 + lane] = make_float4(p_reg[4], p_reg[4], p_reg[5], p_reg[5]);
        pw[96 + lane] = make_float4(p_reg[6], p_reg[6], p_reg[7], p_reg[7]);
        __syncwarp();

        const ulonglong2* pwu = (const ulonglong2*)pw;
#pragma unroll 2
        for (int jj = 0; jj < 32; jj++) {
            ulonglong2 P0 = pwu[jj];          // (p0,p0),(p1,p1)  broadcast LDS.128
            ulonglong2 P1 = pwu[32 + jj];     // (p2,p2),(p3,p3)
            ulonglong2 P2 = pwu[64 + jj];
            ulonglong2 P3 = pwu[96 + jj];
            ulonglong2 vA = *(const ulonglong2*)(v_s + jj * 256 + lane * 4);
            ulonglong2 vB = *(const ulonglong2*)(v_s + jj * 256 + 128 + lane * 4);
            acc[0][0] = fma2(P0.x, vA.x, acc[0][0]); acc[0][1] = fma2(P0.x, vA.y, acc[0][1]);
            acc[0][2] = fma2(P0.x, vB.x, acc[0][2]); acc[0][3] = fma2(P0.x, vB.y, acc[0][3]);
            acc[1][0] = fma2(P0.y, vA.x, acc[1][0]); acc[1][1] = fma2(P0.y, vA.y, acc[1][1]);
            acc[1][2] = fma2(P0.y, vB.x, acc[1][2]); acc[1][3] = fma2(P0.y, vB.y, acc[1][3]);
            acc[2][0] = fma2(P1.x, vA.x, acc[2][0]); acc[2][1] = fma2(P1.x, vA.y, acc[2][1]);
            acc[2][2] = fma2(P1.x, vB.x, acc[2][2]); acc[2][3] = fma2(P1.x, vB.y, acc[2][3]);
            acc[3][0] = fma2(P1.y, vA.x, acc[3][0]); acc[3][1] = fma2(P1.y, vA.y, acc[3][1]);
            acc[3][2] = fma2(P1.y, vB.x, acc[3][2]); acc[3][3] = fma2(P1.y, vB.y, acc[3][3]);
            acc[4][0] = fma2(P2.x, vA.x, acc[4][0]); acc[4][1] = fma2(P2.x, vA.y, acc[4][1]);
            acc[4][2] = fma2(P2.x, vB.x, acc[4][2]); acc[4][3] = fma2(P2.x, vB.y, acc[4][3]);
            acc[5][0] = fma2(P2.y, vA.x, acc[5][0]); acc[5][1] = fma2(P2.y, vA.y, acc[5][1]);
            acc[5][2] = fma2(P2.y, vB.x, acc[5][2]); acc[5][3] = fma2(P2.y, vB.y, acc[5][3]);
            acc[6][0] = fma2(P3.x, vA.x, acc[6][0]); acc[6][1] = fma2(P3.x, vA.y, acc[6][1]);
            acc[6][2] = fma2(P3.x, vB.x, acc[6][2]); acc[6][3] = fma2(P3.x, vB.y, acc[6][3]);
            acc[7][0] = fma2(P3.y, vA.x, acc[7][0]); acc[7][1] = fma2(P3.y, vA.y, acc[7][1]);
            acc[7][2] = fma2(P3.y, vB.x, acc[7][2]); acc[7][3] = fma2(P3.y, vB.y, acc[7][3]);
        }
        CP_WAIT0;
        __syncthreads();
    }
#pragma unroll
    for (int q = 0; q < 8; q++) {
        float d = den[q];
#pragma unroll
        for (int o = 16; o > 0; o >>= 1) d += __shfl_xor_sync(0xffffffffu, d, o);
        float r = 1.0f / d;
        int pix = pix_of(l0 + warp * 8 + q);
        float* outp = g_ctx + ((size_t)batch * 8192 + pix) * 1024 + sidx * 256;
        float a0, a1, a2, a3, b0, b1, b2, b3;
        unpack2(acc[q][0], a0, a1); unpack2(acc[q][1], a2, a3);
        unpack2(acc[q][2], b0, b1); unpack2(acc[q][3], b2, b3);
        *(float4*)(outp + lane * 4) = make_float4(a0 * r, a1 * r, a2 * r, a3 * r);
        *(float4*)(outp + 128 + lane * 4) = make_float4(b0 * r, b1 * r, b2 * r, b3 * r);
    }
}

// ---- 5) 3x3 conv + BN + ReLU: 64 px x 128 oc, double-buffered (cp.async B, reg-prefetch A) ----
__global__ void __launch_bounds__(256) conv3(float* __restrict__ out) {
    __shared__ __align__(16) float As[2][16][64];    // [buf][ci][pixel]
    __shared__ __align__(16) float Bs[2][16][128];   // [buf][ci][oc]
    const int tid = threadIdx.x, tx = tid & 15, ty = tid >> 4;
    const int m0 = blockIdx.x << 6, n0 = blockIdx.y << 7;
    const int b = m0 >> 13, pixbase = m0 & 8191;
    const int y = pixbase >> 7, xbase = pixbase & 127;
    const int lp = tid >> 2, lc = (tid & 3) << 2;
    const int lx = xbase + lp;
    const int br = tid >> 4, bc = (tid & 15) << 3;
    const float* ctxb = g_ctx + (size_t)b * 8192 * 1024;
    const unsigned bs_addr = (unsigned)__cvta_generic_to_shared(&Bs[0][0][0]);

    u64 acc[8][2];
#pragma unroll
    for (int i = 0; i < 8; i++) { acc[i][0] = 0; acc[i][1] = 0; }
    const int NK = 576;
    float4 av;

    auto stageA = [&](int kb) {
        int tap = kb >> 6;
        int ny = y + tap / 3 - 1, nx = lx + tap % 3 - 1;
        int ci = (kb & 63) << 4;
        av = make_float4(0.f, 0.f, 0.f, 0.f);
        if (ny >= 0 && ny < 64 && nx >= 0 && nx < 128)
            av = *(const float4*)(ctxb + (size_t)(ny * 128 + nx) * 1024 + ci + lc);
    };
    auto storeA = [&](int buf) {
        As[buf][lc][lp] = av.x; As[buf][lc + 1][lp] = av.y;
        As[buf][lc + 2][lp] = av.z; As[buf][lc + 3][lp] = av.w;
    };
    auto stageB = [&](int kb, int buf) {
        const float* wsrc = g_wt + (size_t)((kb << 4) + br) * 256 + n0 + bc;
        unsigned dst = bs_addr + (buf * 2048 + br * 128 + bc) * 4;
        cp16(dst, wsrc);
        cp16(dst + 16, wsrc + 4);
    };

    stageA(0); storeA(0);
    stageB(0, 0); CP_COMMIT; CP_WAIT0;
    __syncthreads();

    for (int kb = 0; kb < NK; kb++) {
        int buf = kb & 1;
        if (kb + 1 < NK) {
            stageA(kb + 1);
            stageB(kb + 1, buf ^ 1); CP_COMMIT;
        }
#pragma unroll
        for (int kk = 0; kk < 16; kk++) {
            ulonglong2 p2 = *(const ulonglong2*)&As[buf][kk][tx * 4];
            float4 w0 = *(const float4*)&Bs[buf][kk][ty * 8];
            float4 w1 = *(const float4*)&Bs[buf][kk][ty * 8 + 4];
            float wv[8] = {w0.x, w0.y, w0.z, w0.w, w1.x, w1.y, w1.z, w1.w};
#pragma unroll
            for (int i2 = 0; i2 < 8; i2++) {
                u64 w2 = pack2(wv[i2], wv[i2]);
                acc[i2][0] = fma2(w2, p2.x, acc[i2][0]);
                acc[i2][1] = fma2(w2, p2.y, acc[i2][1]);
            }
        }
        if (kb + 1 < NK) storeA(buf ^ 1);
        CP_WAIT0;
        __syncthreads();
    }

#pragma unroll
    for (int i2 = 0; i2 < 8; i2++) {
        int o = n0 + ty * 8 + i2;
        float bb = g_bout[o];
        float a0, a1, a2, a3;
        unpack2(acc[i2][0], a0, a1); unpack2(acc[i2][1], a2, a3);
        *(float4*)(out + (size_t)(b * 256 + o) * 8192 + pixbase + tx * 4) =
            make_float4(fmaxf(a0 + bb, 0.f), fmaxf(a1 + bb, 0.f),
                        fmaxf(a2 + bb, 0.f), fmaxf(a3 + bb, 0.f));
    }
}

extern "C" void kernel_launch(void* const* d_in, const int* in_sizes, int n_in,
                              void* d_out, int out_size) {
    const float* feats = (const float*)d_in[0];
    cudaFuncSetAttribute(attn, cudaFuncAttributeMaxDynamicSharedMemorySize,
                         ATTN_SMEM_FLOATS * 4);
    prep_qkv<<<1280, 256>>>((const float*)d_in[1], (const float*)d_in[2], (const float*)d_in[3],
                            (const float*)d_in[4], (const float*)d_in[5], (const float*)d_in[6],
                            (const float*)d_in[7], (const float*)d_in[8], (const float*)d_in[9],
                            (const float*)d_in[10], (const float*)d_in[11], (const float*)d_in[12],
                            (const float*)d_in[13], (const float*)d_in[14]);
    prep_conv<<<9216, 256>>>((const float*)d_in[15], (const float*)d_in[16], (const float*)d_in[17],
                             (const float*)d_in[18], (const float*)d_in[19], (const float*)d_in[20]);
    gemm_qkv<<<dim3(256, 20), 256>>>(feats);
    attn<<<1024, 256, ATTN_SMEM_FLOATS * 4>>>();
    conv3<<<dim3(256, 2), 256>>>((float*)d_out);
}

// round 14
// speedup vs baseline: 1.0291x; 1.0291x over previous
#include <cuda_runtime.h>

#define EPS 1e-5f

// scratch (static device globals, no allocation)
__device__ float g_weff_t[256 * 1280];                // [cin][ocg]
__device__ float g_beff[1280];
__device__ float g_wt[9216 * 256];                    // [(tap*1024+ci)][oc], BN-scaled
__device__ float g_bout[256];
__device__ float g_qkv[(size_t)2 * 8192 * 1280];      // [b][pix][ocg]
__device__ float g_ctx[(size_t)2 * 8192 * 1024];      // [b][pix][4*256]

typedef unsigned long long u64;
__device__ __forceinline__ u64 pack2(float a, float b) {
    u64 r; asm("mov.b64 %0, {%1, %2};" : "=l"(r) : "f"(a), "f"(b)); return r;
}
__device__ __forceinline__ void unpack2(u64 v, float& a, float& b) {
    asm("mov.b64 {%0, %1}, %2;" : "=f"(a), "=f"(b) : "l"(v));
}
__device__ __forceinline__ u64 fma2(u64 a, u64 b, u64 c) {
    u64 d; asm("fma.rn.f32x2 %0, %1, %2, %3;" : "=l"(d) : "l"(a), "l"(b), "l"(c)); return d;
}
__device__ __forceinline__ u64 mul2(u64 a, u64 b) {
    u64 d; asm("mul.rn.f32x2 %0, %1, %2;" : "=l"(d) : "l"(a), "l"(b)); return d;
}
__device__ __forceinline__ void cp8(unsigned dst, const void* src) {
    asm volatile("cp.async.ca.shared.global [%0], [%1], 8;" :: "r"(dst), "l"(src));
}
__device__ __forceinline__ void cp16(unsigned dst, const void* src) {
    asm volatile("cp.async.cg.shared.global [%0], [%1], 16;" :: "r"(dst), "l"(src));
}
#define CP_COMMIT asm volatile("cp.async.commit_group;" ::: "memory")
#define CP_WAIT0  asm volatile("cp.async.wait_group 0;" ::: "memory")

// ---- 1) fold conv1x1 + BN ----
__global__ void prep_qkv(const float* qw, const float* qb, const float* qg, const float* qbe,
                         const float* qm, const float* qv, const float* kw, const float* kb,
                         const float* kg, const float* kbe, const float* km, const float* kvv,
                         const float* vw, const float* vb) {
    int ocg = blockIdx.x;
    int s = ocg / 320, r = ocg % 320;
    float sc, be; const float* wsrc;
    if (r < 32) {
        int d = s * 32 + r;
        sc = qg[d] * rsqrtf(qv[d] + EPS);
        be = qb[d] * sc + qbe[d] - qm[d] * sc;
        wsrc = qw + (size_t)d * 256;
    } else if (r < 64) {
        int d = s * 32 + (r - 32);
        sc = kg[d] * rsqrtf(kvv[d] + EPS);
        be = kb[d] * sc + kbe[d] - km[d] * sc;
        wsrc = kw + (size_t)d * 256;
    } else {
        int d = s * 256 + (r - 64);
        sc = 1.0f; be = vb[d];
        wsrc = vw + (size_t)d * 256;
    }
    for (int c = threadIdx.x; c < 256; c += blockDim.x)
        g_weff_t[c * 1280 + ocg] = wsrc[c] * sc;
    if (threadIdx.x == 0) g_beff[ocg] = be;
}

// ---- 2) fold BN into transposed 3x3 weights ----
__global__ void prep_conv(const float* cw, const float* cb, const float* cg,
                          const float* cbe, const float* cm, const float* cv) {
    int blk = blockIdx.x;                 // tap*1024 + ci
    int o = threadIdx.x;
    float sc = cg[o] * rsqrtf(cv[o] + EPS);
    g_wt[(size_t)blk * 256 + o] =
        cw[((size_t)o * 1024 + (blk & 1023)) * 9 + (blk >> 10)] * sc;
    if (blk == 0) g_bout[o] = cb[o] * sc + cbe[o] - cm[o] * sc;
}

// ---- 3) fused QKV GEMM ----
__global__ void __launch_bounds__(256) gemm_qkv(const float* __restrict__ feats) {
    __shared__ __align__(16) float As[16][64];
    __shared__ __align__(16) float Bs[16][64];
    const int tid = threadIdx.x, tx = tid & 15, ty = tid >> 4;
    const int m0 = blockIdx.x << 6, n0 = blockIdx.y << 6;
    const int b = m0 >> 13, pix0 = m0 & 8191;
    u64 acc[4][2];
#pragma unroll
    for (int i = 0; i < 4; i++) { acc[i][0] = 0; acc[i][1] = 0; }
    for (int c0 = 0; c0 < 256; c0 += 16) {
        __syncthreads();
#pragma unroll
        for (int it = 0; it < 4; it++) {
            int idx = tid + it * 256, kk = idx >> 6, mm = idx & 63;
            As[kk][mm] = feats[(size_t)(b * 256 + c0 + kk) * 8192 + pix0 + mm];
            Bs[kk][mm] = g_weff_t[(size_t)(c0 + kk) * 1280 + n0 + mm];
        }
        __syncthreads();
#pragma unroll
        for (int kk = 0; kk < 16; kk++) {
            ulonglong2 b2 = *(const ulonglong2*)&Bs[kk][tx * 4];
#pragma unroll
            for (int i2 = 0; i2 < 4; i2++) {
                float a = As[kk][ty * 4 + i2];
                u64 a2 = pack2(a, a);
                acc[i2][0] = fma2(a2, b2.x, acc[i2][0]);
                acc[i2][1] = fma2(a2, b2.y, acc[i2][1]);
            }
        }
    }
    const float4 bias = *(const float4*)(g_beff + n0 + tx * 4);
#pragma unroll
    for (int i2 = 0; i2 < 4; i2++) {
        float a0, a1, a2, a3;
        unpack2(acc[i2][0], a0, a1);
        unpack2(acc[i2][1], a2, a3);
        *(float4*)(g_qkv + (size_t)(m0 + ty * 4 + i2) * 1280 + n0 + tx * 4) =
            make_float4(a0 + bias.x, a1 + bias.y, a2 + bias.z, a3 + bias.w);
    }
}

// ---- 4) windowed attention: 256 thr, 8 warps x 8 queries; smem p-table (R12 best) ----
#define ATTN_SMEM_FLOATS (2048 + 2 * 1088 + 2 * 8192 + 2048)
__global__ void __launch_bounds__(256, 1) attn() {
    extern __shared__ __align__(16) float smf[];
    float* q_s = smf;
    float* k_sb = smf + 2048;
    float* v_sb = smf + 4224;
    float4* p4 = (float4*)(smf + 20608);
    const unsigned k_addr = (unsigned)__cvta_generic_to_shared(k_sb);
    const unsigned v_addr = (unsigned)__cvta_generic_to_shared(v_sb);

    const int tid = threadIdx.x, lane = tid & 31, warp = tid >> 5;   // 8 warps
    const int bid = blockIdx.x;
    const int sidx = bid >> 8, within = bid & 255;
    const int shift = 6 - sidx;
    const int ws = 64 >> sidx;
    const int L = 8192 >> (2 * sidx);
    const int bpwLog = 7 - 2 * sidx;
    const int win = within >> bpwLog;
    const int qblk = within & ((1 << bpwLog) - 1);
    const int batch = win & 1;
    const int ij = win >> 1;
    const int wi = ij >> sidx, wj = ij & ((1 << sidx) - 1);
    const int l0 = qblk << 6;
    const float* qkv_b = g_qkv + (size_t)batch * 8192 * 1280;
    const int chbase = sidx * 320;

    auto pix_of = [&](int l) -> int {
        int half = l & 1, rc = l >> 1;
        int r = rc >> shift, c = rc & (ws - 1);
        return (wi * ws + r) * 128 + half * 64 + wj * ws + c;
    };

    // load queries (once)
    for (int idx = tid; idx < 1024; idx += 256) {
        int ql = idx >> 4, c2 = idx & 15;
        float2 v = *(const float2*)(qkv_b + (size_t)pix_of(l0 + ql) * 1280 + chbase + c2 * 2);
        q_s[ql * 32 + c2 * 2] = v.x; q_s[ql * 32 + c2 * 2 + 1] = v.y;
    }

    auto load_tile = [&](int t, int buf) {
        int m0 = t << 5;
#pragma unroll
        for (int i = 0; i < 2; i++) {   // k tile: 32 keys x 16 ch-pairs
            int idx = tid + i * 256;
            int key = idx >> 4, c2 = idx & 15;
            const float* src = qkv_b + (size_t)pix_of(m0 + key) * 1280 + chbase + 32 + c2 * 2;
            cp8(k_addr + (buf * 1088 + key * 34 + c2 * 2) * 4, src);
        }
#pragma unroll
        for (int i = 0; i < 8; i++) {   // v tile: 32 keys x 64 float4
            int idx = tid + i * 256;
            int key = idx >> 6, c4 = idx & 63;
            const float* src = qkv_b + (size_t)pix_of(m0 + key) * 1280 + chbase + 64 + c4 * 4;
            cp16(v_addr + (buf * 8192 + key * 256 + c4 * 4) * 4, src);
        }
    };

    float den[8], p_reg[8];
    u64 acc[8][4];
#pragma unroll
    for (int q = 0; q < 8; q++) {
        den[q] = 0.f;
        acc[q][0] = acc[q][1] = acc[q][2] = acc[q][3] = 0;
    }
    const float* qbase = q_s + (warp * 8) * 32;
    float4* pw = p4 + warp * 64;
    const int nt = L >> 5;

    load_tile(0, 0);
    CP_COMMIT;
    CP_WAIT0;
    __syncthreads();

    for (int t = 0; t < nt; t++) {
        int buf = t & 1;
        if (t + 1 < nt) { load_tile(t + 1, buf ^ 1); CP_COMMIT; }

        const float* k_s = k_sb + buf * 1088;
        const float* v_s = v_sb + buf * 8192;

        u64 k2[16];
        const u64* krow = (const u64*)(k_s + lane * 34);
#pragma unroll
        for (int d = 0; d < 16; d++) k2[d] = krow[d];

#pragma unroll
        for (int q = 0; q < 8; q++) {
            const u64* qrow = (const u64*)(qbase + q * 32);
            u64 sA = 0, sB = 0;            // two chains for ILP
#pragma unroll
            for (int d = 0; d < 8; d++) {
                sA = fma2(k2[d], qrow[d], sA);
                sB = fma2(k2[d + 8], qrow[d + 8], sB);
            }
            float a0, a1, b0, b1;
            unpack2(sA, a0, a1); unpack2(sB, b0, b1);
            float p = __expf((a0 + a1 + b0 + b1) * 0.17677669529663687f);
            den[q] += p;
            p_reg[q] = p;
        }
        // lane = key: publish its 8 probabilities (q fastest, conflict-free STS.128)
        pw[lane] = make_float4(p_reg[0], p_reg[1], p_reg[2], p_reg[3]);
        pw[32 + lane] = make_float4(p_reg[4], p_reg[5], p_reg[6], p_reg[7]);
        __syncwarp();

#pragma unroll 2
        for (int jj = 0; jj < 32; jj++) {
            float4 pa = pw[jj];          // broadcast LDS.128: p for q0..q3
            float4 pb = pw[32 + jj];     // broadcast LDS.128: p for q4..q7
            ulonglong2 vA = *(const ulonglong2*)(v_s + jj * 256 + lane * 4);
            ulonglong2 vB = *(const ulonglong2*)(v_s + jj * 256 + 128 + lane * 4);
            u64 pp[8];
            pp[0] = pack2(pa.x, pa.x); pp[1] = pack2(pa.y, pa.y);
            pp[2] = pack2(pa.z, pa.z); pp[3] = pack2(pa.w, pa.w);
            pp[4] = pack2(pb.x, pb.x); pp[5] = pack2(pb.y, pb.y);
            pp[6] = pack2(pb.z, pb.z); pp[7] = pack2(pb.w, pb.w);
#pragma unroll
            for (int q = 0; q < 8; q++) {
                acc[q][0] = fma2(pp[q], vA.x, acc[q][0]);
                acc[q][1] = fma2(pp[q], vA.y, acc[q][1]);
                acc[q][2] = fma2(pp[q], vB.x, acc[q][2]);
                acc[q][3] = fma2(pp[q], vB.y, acc[q][3]);
            }
        }
        CP_WAIT0;
        __syncthreads();
    }
#pragma unroll
    for (int q = 0; q < 8; q++) {
        float d = den[q];
#pragma unroll
        for (int o = 16; o > 0; o >>= 1) d += __shfl_xor_sync(0xffffffffu, d, o);
        float r = 1.0f / d;
        int pix = pix_of(l0 + warp * 8 + q);
        float* outp = g_ctx + ((size_t)batch * 8192 + pix) * 1024 + sidx * 256;
        float a0, a1, a2, a3, b0, b1, b2, b3;
        unpack2(acc[q][0], a0, a1); unpack2(acc[q][1], a2, a3);
        unpack2(acc[q][2], b0, b1); unpack2(acc[q][3], b2, b3);
        *(float4*)(outp + lane * 4) = make_float4(a0 * r, a1 * r, a2 * r, a3 * r);
        *(float4*)(outp + 128 + lane * 4) = make_float4(b0 * r, b1 * r, b2 * r, b3 * r);
    }
}

// ---- 5) 3x3 conv + BN + ReLU: 128 px x 128 oc tiles, 8 px x 8 oc per thread ----
__global__ void __launch_bounds__(256) conv3(float* __restrict__ out) {
    __shared__ __align__(16) float As[2][16][128];   // [buf][ci][pixel]
    __shared__ __align__(16) float Bs[2][16][128];   // [buf][ci][oc]
    const int tid = threadIdx.x, tx = tid & 15, ty = tid >> 4;
    const int bx = blockIdx.x;              // 0..127 : b*64 + y
    const int b = bx >> 6, y = bx & 63;
    const int n0 = blockIdx.y << 7;
    const int lp = tid >> 1, lc8 = (tid & 1) << 3;   // loader: pixel, ci-offset
    const int br = tid >> 4, bc = (tid & 15) << 3;
    const float* ctxb = g_ctx + (size_t)b * 8192 * 1024;
    const unsigned bs_addr = (unsigned)__cvta_generic_to_shared(&Bs[0][0][0]);

    u64 acc[8][4];
#pragma unroll
    for (int i = 0; i < 8; i++)
        acc[i][0] = acc[i][1] = acc[i][2] = acc[i][3] = 0;
    const int NK = 576;
    float4 av0, av1;

    auto stageA = [&](int kb) {             // 32B contiguous per thread
        int tap = kb >> 6;
        int ny = y + tap / 3 - 1, nx = lp + tap % 3 - 1;
        int ci = ((kb & 63) << 4) + lc8;
        av0 = make_float4(0.f, 0.f, 0.f, 0.f); av1 = av0;
        if (ny >= 0 && ny < 64 && nx >= 0 && nx < 128) {
            const float* base = ctxb + (size_t)(ny * 128 + nx) * 1024 + ci;
            av0 = *(const float4*)base;
            av1 = *(const float4*)(base + 4);
        }
    };
    auto storeA = [&](int buf) {
        As[buf][lc8 + 0][lp] = av0.x; As[buf][lc8 + 1][lp] = av0.y;
        As[buf][lc8 + 2][lp] = av0.z; As[buf][lc8 + 3][lp] = av0.w;
        As[buf][lc8 + 4][lp] = av1.x; As[buf][lc8 + 5][lp] = av1.y;
        As[buf][lc8 + 6][lp] = av1.z; As[buf][lc8 + 7][lp] = av1.w;
    };
    auto stageB = [&](int kb, int buf) {
        const float* wsrc = g_wt + (size_t)((kb << 4) + br) * 256 + n0 + bc;
        unsigned dst = bs_addr + (buf * 2048 + br * 128 + bc) * 4;
        cp16(dst, wsrc);
        cp16(dst + 16, wsrc + 4);
    };

    stageA(0); storeA(0);
    stageB(0, 0); CP_COMMIT; CP_WAIT0;
    __syncthreads();

    for (int kb = 0; kb < NK; kb++) {
        int buf = kb & 1;
        if (kb + 1 < NK) {
            stageA(kb + 1);
            stageB(kb + 1, buf ^ 1); CP_COMMIT;
        }
#pragma unroll
        for (int kk = 0; kk < 16; kk++) {
            ulonglong2 a01 = *(const ulonglong2*)&As[buf][kk][tx * 8];
            ulonglong2 a23 = *(const ulonglong2*)&As[buf][kk][tx * 8 + 4];
            float4 w0 = *(const float4*)&Bs[buf][kk][ty * 8];
            float4 w1 = *(const float4*)&Bs[buf][kk][ty * 8 + 4];
            float wv[8] = {w0.x, w0.y, w0.z, w0.w, w1.x, w1.y, w1.z, w1.w};
#pragma unroll
            for (int i2 = 0; i2 < 8; i2++) {
                u64 w2 = pack2(wv[i2], wv[i2]);
                acc[i2][0] = fma2(w2, a01.x, acc[i2][0]);
                acc[i2][1] = fma2(w2, a01.y, acc[i2][1]);
                acc[i2][2] = fma2(w2, a23.x, acc[i2][2]);
                acc[i2][3] = fma2(w2, a23.y, acc[i2][3]);
            }
        }
        if (kb + 1 < NK) storeA(buf ^ 1);
        CP_WAIT0;
        __syncthreads();
    }

#pragma unroll
    for (int i2 = 0; i2 < 8; i2++) {
        int o = n0 + ty * 8 + i2;
        float bb = g_bout[o];
        float p0, p1, p2, p3, p4, p5, p6, p7;
        unpack2(acc[i2][0], p0, p1); unpack2(acc[i2][1], p2, p3);
        unpack2(acc[i2][2], p4, p5); unpack2(acc[i2][3], p6, p7);
        float* op = out + (size_t)(b * 256 + o) * 8192 + y * 128 + tx * 8;
        *(float4*)op = make_float4(fmaxf(p0 + bb, 0.f), fmaxf(p1 + bb, 0.f),
                                   fmaxf(p2 + bb, 0.f), fmaxf(p3 + bb, 0.f));
        *(float4*)(op + 4) = make_float4(fmaxf(p4 + bb, 0.f), fmaxf(p5 + bb, 0.f),
                                         fmaxf(p6 + bb, 0.f), fmaxf(p7 + bb, 0.f));
    }
}

extern "C" void kernel_launch(void* const* d_in, const int* in_sizes, int n_in,
                              void* d_out, int out_size) {
    const float* feats = (const float*)d_in[0];
    cudaFuncSetAttribute(attn, cudaFuncAttributeMaxDynamicSharedMemorySize,
                         ATTN_SMEM_FLOATS * 4);
    prep_qkv<<<1280, 256>>>((const float*)d_in[1], (const float*)d_in[2], (const float*)d_in[3],
                            (const float*)d_in[4], (const float*)d_in[5], (const float*)d_in[6],
                            (const float*)d_in[7], (const float*)d_in[8], (const float*)d_in[9],
                            (const float*)d_in[10], (const float*)d_in[11], (const float*)d_in[12],
                            (const float*)d_in[13], (const float*)d_in[14]);
    prep_conv<<<9216, 256>>>((const float*)d_in[15], (const float*)d_in[16], (const float*)d_in[17],
                             (const float*)d_in[18], (const float*)d_in[19], (const float*)d_in[20]);
    gemm_qkv<<<dim3(256, 20), 256>>>(feats);
    attn<<<1024, 256, ATTN_SMEM_FLOATS * 4>>>();
    conv3<<<dim3(128, 2), 256>>>((float*)d_out);
}

// round 15
// speedup vs baseline: 1.0618x; 1.0318x over previous
#include <cuda_runtime.h>

#define EPS 1e-5f

// scratch (static device globals, no allocation)
__device__ float g_weff_t[256 * 1280];                // [cin][ocg]
__device__ float g_beff[1280];
__device__ float g_wt[9216 * 256];                    // [(tap*1024+ci)][oc], BN-scaled
__device__ float g_bout[256];
__device__ float g_qkv[(size_t)2 * 8192 * 1280];      // [b][pix][ocg]
__device__ float g_ctx[(size_t)2 * 8192 * 1024];      // [b][pix][4*256]

typedef unsigned long long u64;
__device__ __forceinline__ u64 pack2(float a, float b) {
    u64 r; asm("mov.b64 %0, {%1, %2};" : "=l"(r) : "f"(a), "f"(b)); return r;
}
__device__ __forceinline__ void unpack2(u64 v, float& a, float& b) {
    asm("mov.b64 {%0, %1}, %2;" : "=f"(a), "=f"(b) : "l"(v));
}
__device__ __forceinline__ u64 fma2(u64 a, u64 b, u64 c) {
    u64 d; asm("fma.rn.f32x2 %0, %1, %2, %3;" : "=l"(d) : "l"(a), "l"(b), "l"(c)); return d;
}
__device__ __forceinline__ u64 mul2(u64 a, u64 b) {
    u64 d; asm("mul.rn.f32x2 %0, %1, %2;" : "=l"(d) : "l"(a), "l"(b)); return d;
}
__device__ __forceinline__ void cp8(unsigned dst, const void* src) {
    asm volatile("cp.async.ca.shared.global [%0], [%1], 8;" :: "r"(dst), "l"(src));
}
__device__ __forceinline__ void cp16(unsigned dst, const void* src) {
    asm volatile("cp.async.cg.shared.global [%0], [%1], 16;" :: "r"(dst), "l"(src));
}
#define CP_COMMIT asm volatile("cp.async.commit_group;" ::: "memory")
#define CP_WAIT0  asm volatile("cp.async.wait_group 0;" ::: "memory")

// ---- 1) fold conv1x1 + BN ----
__global__ void prep_qkv(const float* qw, const float* qb, const float* qg, const float* qbe,
                         const float* qm, const float* qv, const float* kw, const float* kb,
                         const float* kg, const float* kbe, const float* km, const float* kvv,
                         const float* vw, const float* vb) {
    int ocg = blockIdx.x;
    int s = ocg / 320, r = ocg % 320;
    float sc, be; const float* wsrc;
    if (r < 32) {
        int d = s * 32 + r;
        sc = qg[d] * rsqrtf(qv[d] + EPS);
        be = qb[d] * sc + qbe[d] - qm[d] * sc;
        wsrc = qw + (size_t)d * 256;
    } else if (r < 64) {
        int d = s * 32 + (r - 32);
        sc = kg[d] * rsqrtf(kvv[d] + EPS);
        be = kb[d] * sc + kbe[d] - km[d] * sc;
        wsrc = kw + (size_t)d * 256;
    } else {
        int d = s * 256 + (r - 64);
        sc = 1.0f; be = vb[d];
        wsrc = vw + (size_t)d * 256;
    }
    for (int c = threadIdx.x; c < 256; c += blockDim.x)
        g_weff_t[c * 1280 + ocg] = wsrc[c] * sc;
    if (threadIdx.x == 0) g_beff[ocg] = be;
}

// ---- 2) fold BN into transposed 3x3 weights ----
__global__ void prep_conv(const float* cw, const float* cb, const float* cg,
                          const float* cbe, const float* cm, const float* cv) {
    int blk = blockIdx.x;                 // tap*1024 + ci
    int o = threadIdx.x;
    float sc = cg[o] * rsqrtf(cv[o] + EPS);
    g_wt[(size_t)blk * 256 + o] =
        cw[((size_t)o * 1024 + (blk & 1023)) * 9 + (blk >> 10)] * sc;
    if (blk == 0) g_bout[o] = cb[o] * sc + cbe[o] - cm[o] * sc;
}

// ---- 3) fused QKV GEMM, cp.async double-buffered ----
__global__ void __launch_bounds__(256) gemm_qkv(const float* __restrict__ feats) {
    __shared__ __align__(16) float As[2][16][64];
    __shared__ __align__(16) float Bs[2][16][64];
    const int tid = threadIdx.x, tx = tid & 15, ty = tid >> 4;
    const int m0 = blockIdx.x << 6, n0 = blockIdx.y << 6;
    const int b = m0 >> 13, pix0 = m0 & 8191;
    const int kk_l = tid >> 4, mm_l = (tid & 15) << 2;
    const unsigned as_addr = (unsigned)__cvta_generic_to_shared(&As[0][0][0]);
    const unsigned bs_addr = (unsigned)__cvta_generic_to_shared(&Bs[0][0][0]);

    auto stage = [&](int c0, int buf) {
        cp16(as_addr + (buf * 1024 + kk_l * 64 + mm_l) * 4,
             feats + (size_t)(b * 256 + c0 + kk_l) * 8192 + pix0 + mm_l);
        cp16(bs_addr + (buf * 1024 + kk_l * 64 + mm_l) * 4,
             g_weff_t + (size_t)(c0 + kk_l) * 1280 + n0 + mm_l);
    };

    u64 acc[4][2];
#pragma unroll
    for (int i = 0; i < 4; i++) { acc[i][0] = 0; acc[i][1] = 0; }

    stage(0, 0); CP_COMMIT; CP_WAIT0;
    __syncthreads();

    for (int c0 = 0; c0 < 256; c0 += 16) {
        int buf = (c0 >> 4) & 1;
        if (c0 + 16 < 256) { stage(c0 + 16, buf ^ 1); CP_COMMIT; }
#pragma unroll
        for (int kk = 0; kk < 16; kk++) {
            ulonglong2 b2 = *(const ulonglong2*)&Bs[buf][kk][tx * 4];
#pragma unroll
            for (int i2 = 0; i2 < 4; i2++) {
                float a = As[buf][kk][ty * 4 + i2];
                u64 a2 = pack2(a, a);
                acc[i2][0] = fma2(a2, b2.x, acc[i2][0]);
                acc[i2][1] = fma2(a2, b2.y, acc[i2][1]);
            }
        }
        CP_WAIT0;
        __syncthreads();
    }
    const float4 bias = *(const float4*)(g_beff + n0 + tx * 4);
#pragma unroll
    for (int i2 = 0; i2 < 4; i2++) {
        float a0, a1, a2, a3;
        unpack2(acc[i2][0], a0, a1);
        unpack2(acc[i2][1], a2, a3);
        *(float4*)(g_qkv + (size_t)(m0 + ty * 4 + i2) * 1280 + n0 + tx * 4) =
            make_float4(a0 + bias.x, a1 + bias.y, a2 + bias.z, a3 + bias.w);
    }
}

// ---- 4) windowed attention: 256 thr, 8 warps x 8 queries; smem p-table (R12 best) ----
#define ATTN_SMEM_FLOATS (2048 + 2 * 1088 + 2 * 8192 + 2048)
__global__ void __launch_bounds__(256, 1) attn() {
    extern __shared__ __align__(16) float smf[];
    float* q_s = smf;
    float* k_sb = smf + 2048;
    float* v_sb = smf + 4224;
    float4* p4 = (float4*)(smf + 20608);
    const unsigned k_addr = (unsigned)__cvta_generic_to_shared(k_sb);
    const unsigned v_addr = (unsigned)__cvta_generic_to_shared(v_sb);

    const int tid = threadIdx.x, lane = tid & 31, warp = tid >> 5;   // 8 warps
    const int bid = blockIdx.x;
    const int sidx = bid >> 8, within = bid & 255;
    const int shift = 6 - sidx;
    const int ws = 64 >> sidx;
    const int L = 8192 >> (2 * sidx);
    const int bpwLog = 7 - 2 * sidx;
    const int win = within >> bpwLog;
    const int qblk = within & ((1 << bpwLog) - 1);
    const int batch = win & 1;
    const int ij = win >> 1;
    const int wi = ij >> sidx, wj = ij & ((1 << sidx) - 1);
    const int l0 = qblk << 6;
    const float* qkv_b = g_qkv + (size_t)batch * 8192 * 1280;
    const int chbase = sidx * 320;

    auto pix_of = [&](int l) -> int {
        int half = l & 1, rc = l >> 1;
        int r = rc >> shift, c = rc & (ws - 1);
        return (wi * ws + r) * 128 + half * 64 + wj * ws + c;
    };

    // load queries (once)
    for (int idx = tid; idx < 1024; idx += 256) {
        int ql = idx >> 4, c2 = idx & 15;
        float2 v = *(const float2*)(qkv_b + (size_t)pix_of(l0 + ql) * 1280 + chbase + c2 * 2);
        q_s[ql * 32 + c2 * 2] = v.x; q_s[ql * 32 + c2 * 2 + 1] = v.y;
    }

    auto load_tile = [&](int t, int buf) {
        int m0 = t << 5;
#pragma unroll
        for (int i = 0; i < 2; i++) {   // k tile: 32 keys x 16 ch-pairs
            int idx = tid + i * 256;
            int key = idx >> 4, c2 = idx & 15;
            const float* src = qkv_b + (size_t)pix_of(m0 + key) * 1280 + chbase + 32 + c2 * 2;
            cp8(k_addr + (buf * 1088 + key * 34 + c2 * 2) * 4, src);
        }
#pragma unroll
        for (int i = 0; i < 8; i++) {   // v tile: 32 keys x 64 float4
            int idx = tid + i * 256;
            int key = idx >> 6, c4 = idx & 63;
            const float* src = qkv_b + (size_t)pix_of(m0 + key) * 1280 + chbase + 64 + c4 * 4;
            cp16(v_addr + (buf * 8192 + key * 256 + c4 * 4) * 4, src);
        }
    };

    float den[8], p_reg[8];
    u64 acc[8][4];
#pragma unroll
    for (int q = 0; q < 8; q++) {
        den[q] = 0.f;
        acc[q][0] = acc[q][1] = acc[q][2] = acc[q][3] = 0;
    }
    const float* qbase = q_s + (warp * 8) * 32;
    float4* pw = p4 + warp * 64;
    const int nt = L >> 5;

    load_tile(0, 0);
    CP_COMMIT;
    CP_WAIT0;
    __syncthreads();

    for (int t = 0; t < nt; t++) {
        int buf = t & 1;
        if (t + 1 < nt) { load_tile(t + 1, buf ^ 1); CP_COMMIT; }

        const float* k_s = k_sb + buf * 1088;
        const float* v_s = v_sb + buf * 8192;

        u64 k2[16];
        const u64* krow = (const u64*)(k_s + lane * 34);
#pragma unroll
        for (int d = 0; d < 16; d++) k2[d] = krow[d];

#pragma unroll
        for (int q = 0; q < 8; q++) {
            const u64* qrow = (const u64*)(qbase + q * 32);
            u64 sA = 0, sB = 0;            // two chains for ILP
#pragma unroll
            for (int d = 0; d < 8; d++) {
                sA = fma2(k2[d], qrow[d], sA);
                sB = fma2(k2[d + 8], qrow[d + 8], sB);
            }
            float a0, a1, b0, b1;
            unpack2(sA, a0, a1); unpack2(sB, b0, b1);
            float p = __expf((a0 + a1 + b0 + b1) * 0.17677669529663687f);
            den[q] += p;
            p_reg[q] = p;
        }
        // lane = key: publish its 8 probabilities (q fastest, conflict-free STS.128)
        pw[lane] = make_float4(p_reg[0], p_reg[1], p_reg[2], p_reg[3]);
        pw[32 + lane] = make_float4(p_reg[4], p_reg[5], p_reg[6], p_reg[7]);
        __syncwarp();

#pragma unroll 2
        for (int jj = 0; jj < 32; jj++) {
            float4 pa = pw[jj];          // broadcast LDS.128: p for q0..q3
            float4 pb = pw[32 + jj];     // broadcast LDS.128: p for q4..q7
            ulonglong2 vA = *(const ulonglong2*)(v_s + jj * 256 + lane * 4);
            ulonglong2 vB = *(const ulonglong2*)(v_s + jj * 256 + 128 + lane * 4);
            u64 pp[8];
            pp[0] = pack2(pa.x, pa.x); pp[1] = pack2(pa.y, pa.y);
            pp[2] = pack2(pa.z, pa.z); pp[3] = pack2(pa.w, pa.w);
            pp[4] = pack2(pb.x, pb.x); pp[5] = pack2(pb.y, pb.y);
            pp[6] = pack2(pb.z, pb.z); pp[7] = pack2(pb.w, pb.w);
#pragma unroll
            for (int q = 0; q < 8; q++) {
                acc[q][0] = fma2(pp[q], vA.x, acc[q][0]);
                acc[q][1] = fma2(pp[q], vA.y, acc[q][1]);
                acc[q][2] = fma2(pp[q], vB.x, acc[q][2]);
                acc[q][3] = fma2(pp[q], vB.y, acc[q][3]);
            }
        }
        CP_WAIT0;
        __syncthreads();
    }
#pragma unroll
    for (int q = 0; q < 8; q++) {
        float d = den[q];
#pragma unroll
        for (int o = 16; o > 0; o >>= 1) d += __shfl_xor_sync(0xffffffffu, d, o);
        float r = 1.0f / d;
        int pix = pix_of(l0 + warp * 8 + q);
        float* outp = g_ctx + ((size_t)batch * 8192 + pix) * 1024 + sidx * 256;
        float a0, a1, a2, a3, b0, b1, b2, b3;
        unpack2(acc[q][0], a0, a1); unpack2(acc[q][1], a2, a3);
        unpack2(acc[q][2], b0, b1); unpack2(acc[q][3], b2, b3);
        *(float4*)(outp + lane * 4) = make_float4(a0 * r, a1 * r, a2 * r, a3 * r);
        *(float4*)(outp + 128 + lane * 4) = make_float4(b0 * r, b1 * r, b2 * r, b3 * r);
    }
}

// ---- 5) 3x3 conv + BN + ReLU: 64 px x 128 oc, double-buffered (R12 best) ----
__global__ void __launch_bounds__(256) conv3(float* __restrict__ out) {
    __shared__ __align__(16) float As[2][16][64];    // [buf][ci][pixel]
    __shared__ __align__(16) float Bs[2][16][128];   // [buf][ci][oc]
    const int tid = threadIdx.x, tx = tid & 15, ty = tid >> 4;
    const int m0 = blockIdx.x << 6, n0 = blockIdx.y << 7;
    const int b = m0 >> 13, pixbase = m0 & 8191;
    const int y = pixbase >> 7, xbase = pixbase & 127;
    const int lp = tid >> 2, lc = (tid & 3) << 2;
    const int lx = xbase + lp;
    const int br = tid >> 4, bc = (tid & 15) << 3;
    const float* ctxb = g_ctx + (size_t)b * 8192 * 1024;
    const unsigned bs_addr = (unsigned)__cvta_generic_to_shared(&Bs[0][0][0]);

    u64 acc[8][2];
#pragma unroll
    for (int i = 0; i < 8; i++) { acc[i][0] = 0; acc[i][1] = 0; }
    const int NK = 576;
    float4 av;

    auto stageA = [&](int kb) {
        int tap = kb >> 6;
        int ny = y + tap / 3 - 1, nx = lx + tap % 3 - 1;
        int ci = (kb & 63) << 4;
        av = make_float4(0.f, 0.f, 0.f, 0.f);
        if (ny >= 0 && ny < 64 && nx >= 0 && nx < 128)
            av = *(const float4*)(ctxb + (size_t)(ny * 128 + nx) * 1024 + ci + lc);
    };
    auto storeA = [&](int buf) {
        As[buf][lc][lp] = av.x; As[buf][lc + 1][lp] = av.y;
        As[buf][lc + 2][lp] = av.z; As[buf][lc + 3][lp] = av.w;
    };
    auto stageB = [&](int kb, int buf) {
        const float* wsrc = g_wt + (size_t)((kb << 4) + br) * 256 + n0 + bc;
        unsigned dst = bs_addr + (buf * 2048 + br * 128 + bc) * 4;
        cp16(dst, wsrc);
        cp16(dst + 16, wsrc + 4);
    };

    stageA(0); storeA(0);
    stageB(0, 0); CP_COMMIT; CP_WAIT0;
    __syncthreads();

    for (int kb = 0; kb < NK; kb++) {
        int buf = kb & 1;
        if (kb + 1 < NK) {
            stageA(kb + 1);
            stageB(kb + 1, buf ^ 1); CP_COMMIT;
        }
#pragma unroll
        for (int kk = 0; kk < 16; kk++) {
            ulonglong2 p2 = *(const ulonglong2*)&As[buf][kk][tx * 4];
            float4 w0 = *(const float4*)&Bs[buf][kk][ty * 8];
            float4 w1 = *(const float4*)&Bs[buf][kk][ty * 8 + 4];
            float wv[8] = {w0.x, w0.y, w0.z, w0.w, w1.x, w1.y, w1.z, w1.w};
#pragma unroll
            for (int i2 = 0; i2 < 8; i2++) {
                u64 w2 = pack2(wv[i2], wv[i2]);
                acc[i2][0] = fma2(w2, p2.x, acc[i2][0]);
                acc[i2][1] = fma2(w2, p2.y, acc[i2][1]);
            }
        }
        if (kb + 1 < NK) storeA(buf ^ 1);
        CP_WAIT0;
        __syncthreads();
    }

#pragma unroll
    for (int i2 = 0; i2 < 8; i2++) {
        int o = n0 + ty * 8 + i2;
        float bb = g_bout[o];
        float a0, a1, a2, a3;
        unpack2(acc[i2][0], a0, a1); unpack2(acc[i2][1], a2, a3);
        *(float4*)(out + (size_t)(b * 256 + o) * 8192 + pixbase + tx * 4) =
            make_float4(fmaxf(a0 + bb, 0.f), fmaxf(a1 + bb, 0.f),
                        fmaxf(a2 + bb, 0.f), fmaxf(a3 + bb, 0.f));
    }
}

extern "C" void kernel_launch(void* const* d_in, const int* in_sizes, int n_in,
                              void* d_out, int out_size) {
    const float* feats = (const float*)d_in[0];
    cudaFuncSetAttribute(attn, cudaFuncAttributeMaxDynamicSharedMemorySize,
                         ATTN_SMEM_FLOATS * 4);
    prep_qkv<<<1280, 256>>>((const float*)d_in[1], (const float*)d_in[2], (const float*)d_in[3],
                            (const float*)d_in[4], (const float*)d_in[5], (const float*)d_in[6],
                            (const float*)d_in[7], (const float*)d_in[8], (const float*)d_in[9],
                            (const float*)d_in[10], (const float*)d_in[11], (const float*)d_in[12],
                            (const float*)d_in[13], (const float*)d_in[14]);
    prep_conv<<<9216, 256>>>((const float*)d_in[15], (const float*)d_in[16], (const float*)d_in[17],
                             (const float*)d_in[18], (const float*)d_in[19], (const float*)d_in[20]);
    gemm_qkv<<<dim3(256, 20), 256>>>(feats);
    attn<<<1024, 256, ATTN_SMEM_FLOATS * 4>>>();
    conv3<<<dim3(256, 2), 256>>>((float*)d_out);
}